// round 1
// baseline (speedup 1.0000x reference)
#include <cuda_runtime.h>
#include <math.h>

#define N_E   8192
#define E_DIM 32
#define T_TOK 32768
#define PAIRS 16384          // 2 tokens per lane: t and t+PAIRS
#define GRID_B 148
#define PAIRS_PER_WARP 28    // ceil(16384 / (148*4))

// scratch (no allocations allowed)
__device__ float g_en [N_E * E_DIM];   // normalized codebook
__device__ float g_en2[N_E];           // sum(en^2) per code (fp32, matches reference d formula)
__device__ float g_part[GRID_B];       // per-block loss partials

typedef unsigned long long ull;

__device__ __forceinline__ ull pack2(float a, float b) {
    ull r; asm("mov.b64 %0, {%1,%2};" : "=l"(r) : "f"(a), "f"(b)); return r;
}
__device__ __forceinline__ void unpack2(ull v, float& a, float& b) {
    asm("mov.b64 {%0,%1}, %2;" : "=f"(a), "=f"(b) : "l"(v));
}
__device__ __forceinline__ ull fma2(ull a, ull b, ull c) {
    ull d; asm("fma.rn.f32x2 %0, %1, %2, %3;" : "=l"(d) : "l"(a), "l"(b), "l"(c)); return d;
}
__device__ __forceinline__ ull add2(ull a, ull b) {
    ull d; asm("add.rn.f32x2 %0, %1, %2;" : "=l"(d) : "l"(a), "l"(b)); return d;
}

// ---------------------------------------------------------------------------
// Kernel A: normalize codebook rows, record fp32 sum of squares of normalized row
// one warp per row (E_DIM == 32 -> one element per lane), coalesced
// ---------------------------------------------------------------------------
__global__ void norm_emb_kernel(const float* __restrict__ emb) {
    int row  = blockIdx.x * 8 + (threadIdx.x >> 5);
    int lane = threadIdx.x & 31;
    float v  = emb[row * E_DIM + lane];
    float ss = v * v;
    #pragma unroll
    for (int o = 16; o; o >>= 1) ss += __shfl_xor_sync(0xFFFFFFFFu, ss, o);
    float inv = 1.0f / fmaxf(sqrtf(ss), 1e-12f);
    float e = v * inv;
    g_en[row * E_DIM + lane] = e;
    float s2 = e * e;
    #pragma unroll
    for (int o = 16; o; o >>= 1) s2 += __shfl_xor_sync(0xFFFFFFFFu, s2, o);
    if (lane == 0) g_en2[row] = s2;
}

// ---------------------------------------------------------------------------
// Kernel B: main VQ. Each active lane owns 2 tokens packed into f32x2 regs.
// Codebook streamed through smem in 128-code chunks, stored DUPLICATED
// ({e,e} per dim) so packed operands come straight from LDS.128.
// ---------------------------------------------------------------------------
__global__ void __launch_bounds__(128) vq_main_kernel(const float* __restrict__ z,
                                                      float* __restrict__ out) {
    __shared__ float s_e[128 * 64];   // 128 codes x 32 dims duplicated = 32 KB
    __shared__ float s_en2[128];
    __shared__ float s_red[128];

    const int tid   = threadIdx.x;
    const int lane  = tid & 31;
    const int gwarp = blockIdx.x * 4 + (tid >> 5);
    const int p     = gwarp * PAIRS_PER_WARP + lane;
    const bool active = (lane < PAIRS_PER_WARP) && (p < PAIRS);
    const int t0 = active ? p : 0;
    const int t1 = active ? (p + PAIRS) : 0;

    // ---- load + normalize the two tokens ----
    float a[E_DIM], b[E_DIM];
    {
        const float4* zA = (const float4*)(z + (size_t)t0 * E_DIM);
        const float4* zB = (const float4*)(z + (size_t)t1 * E_DIM);
        float ssA = 0.0f, ssB = 0.0f;
        #pragma unroll
        for (int j = 0; j < 8; j++) {
            float4 va = zA[j], vb = zB[j];
            a[4*j+0] = va.x; a[4*j+1] = va.y; a[4*j+2] = va.z; a[4*j+3] = va.w;
            b[4*j+0] = vb.x; b[4*j+1] = vb.y; b[4*j+2] = vb.z; b[4*j+3] = vb.w;
            ssA += va.x*va.x + va.y*va.y + va.z*va.z + va.w*va.w;
            ssB += vb.x*vb.x + vb.y*vb.y + vb.z*vb.z + vb.w*vb.w;
        }
        float invA = 1.0f / fmaxf(sqrtf(ssA), 1e-12f);
        float invB = 1.0f / fmaxf(sqrtf(ssB), 1e-12f);
        #pragma unroll
        for (int d = 0; d < E_DIM; d++) { a[d] *= invA; b[d] *= invB; }
    }
    ull zp[E_DIM];
    #pragma unroll
    for (int d = 0; d < E_DIM; d++) zp[d] = pack2(a[d], b[d]);

    float bestA = 3.4e38f, bestB = 3.4e38f;
    int   iA = 0, iB = 0;

    for (int base = 0; base < N_E; base += 128) {
        // cooperative fill: thread tid handles code row tid, writes duplicated dims
        {
            const float4* src = (const float4*)(g_en + (size_t)(base + tid) * E_DIM);
            float4* dst = (float4*)(s_e + tid * 64);
            #pragma unroll
            for (int j = 0; j < 8; j++) {
                float4 v = src[j];
                dst[2*j+0] = make_float4(v.x, v.x, v.y, v.y);
                dst[2*j+1] = make_float4(v.z, v.z, v.w, v.w);
            }
            s_en2[tid] = g_en2[base + tid];
        }
        __syncthreads();

        #pragma unroll 2
        for (int c = 0; c < 128; c++) {
            const ulonglong2* e2 = (const ulonglong2*)(s_e + c * 64);
            ull acc0 = 0ull, acc1 = 0ull, acc2 = 0ull, acc3 = 0ull;
            #pragma unroll
            for (int j = 0; j < 8; j++) {
                ulonglong2 ea = e2[2*j+0];   // {e_{4j},e_{4j}}, {e_{4j+1},e_{4j+1}}
                ulonglong2 eb = e2[2*j+1];   // {e_{4j+2},...},  {e_{4j+3},...}
                acc0 = fma2(zp[4*j+0], ea.x, acc0);
                acc1 = fma2(zp[4*j+1], ea.y, acc1);
                acc2 = fma2(zp[4*j+2], eb.x, acc2);
                acc3 = fma2(zp[4*j+3], eb.y, acc3);
            }
            acc0 = add2(acc0, acc1);
            acc2 = add2(acc2, acc3);
            acc0 = add2(acc0, acc2);
            float dotA, dotB;
            unpack2(acc0, dotA, dotB);
            float en2c = s_en2[c];
            float dA = fmaf(-2.0f, dotA, en2c);
            float dB = fmaf(-2.0f, dotB, en2c);
            int code = base + c;
            if (dA < bestA) { bestA = dA; iA = code; }   // strict < -> first-index ties
            if (dB < bestB) { bestB = dB; iB = code; }
        }
        __syncthreads();
    }

    // ---- epilogue: gather quantized rows, outputs, loss contribution ----
    float lsum = 0.0f;
    if (active) {
        float oa[E_DIM], ob[E_DIM];
        const float* eqA = g_en + (size_t)iA * E_DIM;
        const float* eqB = g_en + (size_t)iB * E_DIM;
        #pragma unroll
        for (int d = 0; d < E_DIM; d++) {
            float za, zb;
            unpack2(zp[d], za, zb);
            float qa = eqA[d], qb = eqB[d];
            float da = qa - za, db = qb - zb;
            lsum += da * da + db * db;
            oa[d] = za + da;      // straight-through: z + (z_q - z)
            ob[d] = zb + db;
        }
        float4* oA = (float4*)(out + (size_t)t0 * E_DIM);
        float4* oB = (float4*)(out + (size_t)t1 * E_DIM);
        #pragma unroll
        for (int j = 0; j < 8; j++) {
            oA[j] = make_float4(oa[4*j], oa[4*j+1], oa[4*j+2], oa[4*j+3]);
            oB[j] = make_float4(ob[4*j], ob[4*j+1], ob[4*j+2], ob[4*j+3]);
        }
        // idx outputs (as float, after z_q_out [1048576 elems] and loss [1])
        out[(size_t)T_TOK * E_DIM + 1 + t0] = (float)iA;
        out[(size_t)T_TOK * E_DIM + 1 + t1] = (float)iB;
    }

    // deterministic block reduction of loss partial
    s_red[tid] = lsum;
    __syncthreads();
    #pragma unroll
    for (int s = 64; s; s >>= 1) {
        if (tid < s) s_red[tid] += s_red[tid + s];
        __syncthreads();
    }
    if (tid == 0) g_part[blockIdx.x] = s_red[0];
}

// ---------------------------------------------------------------------------
// Kernel C: final deterministic loss reduction
// loss = (BETA + 1) * mean((z_q - z)^2) = 1.25 * sum / (T*D)
// ---------------------------------------------------------------------------
__global__ void finish_kernel(float* __restrict__ out) {
    __shared__ float s[256];
    int tid = threadIdx.x;
    s[tid] = (tid < GRID_B) ? g_part[tid] : 0.0f;
    __syncthreads();
    #pragma unroll
    for (int k = 128; k; k >>= 1) {
        if (tid < k) s[tid] += s[tid + k];
        __syncthreads();
    }
    if (tid == 0) out[(size_t)T_TOK * E_DIM] = 1.25f * s[0] / (float)(T_TOK * E_DIM);
}

extern "C" void kernel_launch(void* const* d_in, const int* in_sizes, int n_in,
                              void* d_out, int out_size) {
    const float* z   = (const float*)d_in[0];   // [8,64,64,32] = 1048576 floats
    const float* emb = (const float*)d_in[1];   // [8192,32]    = 262144 floats
    float* out = (float*)d_out;                 // [z_q_out | loss | idx] = 1081345 floats

    norm_emb_kernel<<<N_E / 8, 256>>>(emb);
    vq_main_kernel<<<GRID_B, 128>>>(z, out);
    finish_kernel<<<1, 256>>>(out);
}

// round 2
// speedup vs baseline: 2.4800x; 2.4800x over previous
#include <cuda_runtime.h>
#include <math.h>

#define N_E    8192
#define E_DIM  32
#define T_TOK  32768
#define PAIRS  16384
#define SLICES 8
#define SLICE_CODES 1024
#define CHUNK  128
#define TOK_BLOCKS 128          // 128 blocks x 128 threads = 16384 pairs
#define MERGE_BLOCKS 128        // 128 x 256 = 32768 tokens

// scratch (no allocations allowed)
__device__ float g_en    [N_E * E_DIM];     // normalized codebook (for gather)
__device__ float g_en_dup[N_E * 64];        // duplicated {e,e} rows for packed LDS
__device__ float g_en2   [N_E];             // sum(en^2) per code
__device__ float g_pd    [SLICES * T_TOK];  // per-slice best distance per token
__device__ int   g_pi    [SLICES * T_TOK];  // per-slice best index per token
__device__ float g_part  [MERGE_BLOCKS];    // loss partials

typedef unsigned long long ull;

__device__ __forceinline__ ull pack2(float a, float b) {
    ull r; asm("mov.b64 %0, {%1,%2};" : "=l"(r) : "f"(a), "f"(b)); return r;
}
__device__ __forceinline__ void unpack2(ull v, float& a, float& b) {
    asm("mov.b64 {%0,%1}, %2;" : "=f"(a), "=f"(b) : "l"(v));
}
__device__ __forceinline__ ull fma2(ull a, ull b, ull c) {
    ull d; asm("fma.rn.f32x2 %0, %1, %2, %3;" : "=l"(d) : "l"(a), "l"(b), "l"(c)); return d;
}
__device__ __forceinline__ ull add2(ull a, ull b) {
    ull d; asm("add.rn.f32x2 %0, %1, %2;" : "=l"(d) : "l"(a), "l"(b)); return d;
}

// ---------------------------------------------------------------------------
// Kernel A: normalize codebook rows; emit normal + duplicated layouts + en2
// ---------------------------------------------------------------------------
__global__ void norm_emb_kernel(const float* __restrict__ emb) {
    int row  = blockIdx.x * 8 + (threadIdx.x >> 5);
    int lane = threadIdx.x & 31;
    float v  = emb[row * E_DIM + lane];
    float ss = v * v;
    #pragma unroll
    for (int o = 16; o; o >>= 1) ss += __shfl_xor_sync(0xFFFFFFFFu, ss, o);
    float inv = 1.0f / fmaxf(sqrtf(ss), 1e-12f);
    float e = v * inv;
    g_en[row * E_DIM + lane] = e;
    ((float2*)(g_en_dup + row * 64))[lane] = make_float2(e, e);
    float s2 = e * e;
    #pragma unroll
    for (int o = 16; o; o >>= 1) s2 += __shfl_xor_sync(0xFFFFFFFFu, s2, o);
    if (lane == 0) g_en2[row] = s2;
}

// ---------------------------------------------------------------------------
// Kernel B: distance + per-slice argmin. blockIdx.x = token block (128 pairs),
// blockIdx.y = codebook slice (1024 codes). Each thread: 2 tokens packed f32x2.
// ---------------------------------------------------------------------------
__global__ void __launch_bounds__(128) vq_dist_kernel(const float* __restrict__ z) {
    __shared__ float s_e[CHUNK * 64];     // 32 KB: 128 codes x 32 dims duplicated
    __shared__ float s_en2[CHUNK];

    const int tid   = threadIdx.x;
    const int pair  = blockIdx.x * 128 + tid;
    const int slice = blockIdx.y;
    const int t0 = pair;
    const int t1 = pair + PAIRS;

    // ---- load + normalize the two tokens, pack into f32x2 registers ----
    ull zp[E_DIM];
    {
        float a[E_DIM], b[E_DIM];
        const float4* zA = (const float4*)(z + (size_t)t0 * E_DIM);
        const float4* zB = (const float4*)(z + (size_t)t1 * E_DIM);
        float ssA = 0.0f, ssB = 0.0f;
        #pragma unroll
        for (int j = 0; j < 8; j++) {
            float4 va = zA[j], vb = zB[j];
            a[4*j+0] = va.x; a[4*j+1] = va.y; a[4*j+2] = va.z; a[4*j+3] = va.w;
            b[4*j+0] = vb.x; b[4*j+1] = vb.y; b[4*j+2] = vb.z; b[4*j+3] = vb.w;
            ssA += va.x*va.x + va.y*va.y + va.z*va.z + va.w*va.w;
            ssB += vb.x*vb.x + vb.y*vb.y + vb.z*vb.z + vb.w*vb.w;
        }
        float invA = 1.0f / fmaxf(sqrtf(ssA), 1e-12f);
        float invB = 1.0f / fmaxf(sqrtf(ssB), 1e-12f);
        #pragma unroll
        for (int d = 0; d < E_DIM; d++) zp[d] = pack2(a[d] * invA, b[d] * invB);
    }

    float bestA = 3.4e38f, bestB = 3.4e38f;
    int   iA = 0, iB = 0;

    const int base0 = slice * SLICE_CODES;
    for (int ch = 0; ch < SLICE_CODES / CHUNK; ch++) {
        const int base = base0 + ch * CHUNK;
        // pure float4 copy fill (pre-duplicated in kernel A)
        {
            const float4* src = (const float4*)(g_en_dup + (size_t)(base + tid) * 64);
            float4* dst = (float4*)(s_e + tid * 64);
            #pragma unroll
            for (int j = 0; j < 16; j++) dst[j] = src[j];
            s_en2[tid] = g_en2[base + tid];
        }
        __syncthreads();

        #pragma unroll 2
        for (int c = 0; c < CHUNK; c++) {
            const ulonglong2* e2 = (const ulonglong2*)(s_e + c * 64);
            ull acc0 = 0ull, acc1 = 0ull, acc2 = 0ull, acc3 = 0ull;
            #pragma unroll
            for (int j = 0; j < 8; j++) {
                ulonglong2 ea = e2[2*j+0];
                ulonglong2 eb = e2[2*j+1];
                acc0 = fma2(zp[4*j+0], ea.x, acc0);
                acc1 = fma2(zp[4*j+1], ea.y, acc1);
                acc2 = fma2(zp[4*j+2], eb.x, acc2);
                acc3 = fma2(zp[4*j+3], eb.y, acc3);
            }
            acc0 = add2(acc0, acc1);
            acc2 = add2(acc2, acc3);
            acc0 = add2(acc0, acc2);
            float dotA, dotB;
            unpack2(acc0, dotA, dotB);
            float en2c = s_en2[c];
            float dA = fmaf(-2.0f, dotA, en2c);
            float dB = fmaf(-2.0f, dotB, en2c);
            int code = base + c;
            if (dA < bestA) { bestA = dA; iA = code; }   // strict < -> first-index ties
            if (dB < bestB) { bestB = dB; iB = code; }
        }
        __syncthreads();
    }

    g_pd[slice * T_TOK + t0] = bestA;  g_pi[slice * T_TOK + t0] = iA;
    g_pd[slice * T_TOK + t1] = bestB;  g_pi[slice * T_TOK + t1] = iB;
}

// ---------------------------------------------------------------------------
// Kernel C: merge slices (ascending order, strict <) + gather + outputs + loss
// ---------------------------------------------------------------------------
__global__ void __launch_bounds__(256) vq_merge_kernel(const float* __restrict__ z,
                                                       float* __restrict__ out) {
    __shared__ float s_red[256];
    const int tid = threadIdx.x;
    const int t   = blockIdx.x * 256 + tid;

    float best = g_pd[t];
    int   bi   = g_pi[t];
    #pragma unroll
    for (int s = 1; s < SLICES; s++) {
        float d = g_pd[s * T_TOK + t];
        int  ii = g_pi[s * T_TOK + t];
        if (d < best) { best = d; bi = ii; }
    }

    // load z row, renormalize, gather code row, straight-through + loss
    float zn[E_DIM];
    {
        const float4* zr = (const float4*)(z + (size_t)t * E_DIM);
        float ss = 0.0f;
        #pragma unroll
        for (int j = 0; j < 8; j++) {
            float4 v = zr[j];
            zn[4*j+0] = v.x; zn[4*j+1] = v.y; zn[4*j+2] = v.z; zn[4*j+3] = v.w;
            ss += v.x*v.x + v.y*v.y + v.z*v.z + v.w*v.w;
        }
        float inv = 1.0f / fmaxf(sqrtf(ss), 1e-12f);
        #pragma unroll
        for (int d = 0; d < E_DIM; d++) zn[d] *= inv;
    }

    float lsum = 0.0f;
    float o[E_DIM];
    const float* eq = g_en + (size_t)bi * E_DIM;
    #pragma unroll
    for (int d = 0; d < E_DIM; d++) {
        float q = eq[d];
        float df = q - zn[d];
        lsum += df * df;
        o[d] = zn[d] + df;        // z + (z_q - z), same rounding order as reference
    }
    float4* orow = (float4*)(out + (size_t)t * E_DIM);
    #pragma unroll
    for (int j = 0; j < 8; j++)
        orow[j] = make_float4(o[4*j], o[4*j+1], o[4*j+2], o[4*j+3]);
    out[(size_t)T_TOK * E_DIM + 1 + t] = (float)bi;

    // deterministic block reduction of loss partial
    s_red[tid] = lsum;
    __syncthreads();
    #pragma unroll
    for (int s = 128; s; s >>= 1) {
        if (tid < s) s_red[tid] += s_red[tid + s];
        __syncthreads();
    }
    if (tid == 0) g_part[blockIdx.x] = s_red[0];
}

// ---------------------------------------------------------------------------
// Kernel D: final deterministic loss reduction: 1.25 * sum / (T*D)
// ---------------------------------------------------------------------------
__global__ void finish_kernel(float* __restrict__ out) {
    __shared__ float s[128];
    int tid = threadIdx.x;
    s[tid] = g_part[tid];
    __syncthreads();
    #pragma unroll
    for (int k = 64; k; k >>= 1) {
        if (tid < k) s[tid] += s[tid + k];
        __syncthreads();
    }
    if (tid == 0) out[(size_t)T_TOK * E_DIM] = 1.25f * s[0] / (float)(T_TOK * E_DIM);
}

extern "C" void kernel_launch(void* const* d_in, const int* in_sizes, int n_in,
                              void* d_out, int out_size) {
    const float* z   = (const float*)d_in[0];
    const float* emb = (const float*)d_in[1];
    float* out = (float*)d_out;

    norm_emb_kernel<<<N_E / 8, 256>>>(emb);
    dim3 grid(TOK_BLOCKS, SLICES);
    vq_dist_kernel<<<grid, 128>>>(z);
    vq_merge_kernel<<<MERGE_BLOCKS, 256>>>(z, out);
    finish_kernel<<<1, 128>>>(out);
}

// round 4
// speedup vs baseline: 3.3142x; 1.3364x over previous
#include <cuda_runtime.h>
#include <cuda_fp16.h>
#include <math.h>
#include <stdint.h>

#define N_E    8192
#define E_DIM  32
#define T_TOK  32768
#define KH     192            // halfs per row: 6 blocks of 32
#define KSTEPS 12
#define ROW_B  400            // smem row stride bytes (200 halfs)
#define ROW_W  100            // smem row stride words
#define NCHUNK 128
#define CHUNKS 64
#define MCTA   128
#define GRID_MAIN 256

// ---- device scratch ----
__device__ float  g_en  [N_E * E_DIM];   // normalized codebook fp32 (gather)
__device__ float  g_bias[N_E];           // -0.5 * ||en||^2  (fp32)
__device__ __half g_Bp  [N_E * KH];      // split codebook rows [h1|h1|h1|h2|h2|h3]
__device__ float  g_part[GRID_MAIN];

// ---- smem layout (bytes) ----
#define A_OFF    0
#define B0_OFF   (MCTA * ROW_B)                 // 51200
#define B1_OFF   (B0_OFF + NCHUNK * ROW_B)      // 102400
#define BIAS_OFF (B1_OFF + NCHUNK * ROW_B)      // 153600
#define SMEM_TOTAL (BIAS_OFF + N_E * 4)         // 186368

#define CP_ASYNC16(s, g) asm volatile("cp.async.cg.shared.global [%0], [%1], 16;" :: "r"(s), "l"(g) : "memory")
#define CP_COMMIT()      asm volatile("cp.async.commit_group;" ::: "memory")
#define CP_WAIT1()       asm volatile("cp.async.wait_group 1;" ::: "memory")

__device__ __forceinline__ uint32_t smem_u32(const void* p) {
    uint32_t a;
    asm("{ .reg .u64 t; cvta.to.shared.u64 t, %1; cvt.u32.u64 %0, t; }" : "=r"(a) : "l"(p));
    return a;
}

__device__ __forceinline__ void mma16816(float& c0, float& c1, float& c2, float& c3,
                                         uint32_t a0, uint32_t a1, uint32_t a2, uint32_t a3,
                                         uint32_t b0, uint32_t b1) {
    asm volatile("mma.sync.aligned.m16n8k16.row.col.f32.f16.f16.f32 "
                 "{%0,%1,%2,%3}, {%4,%5,%6,%7}, {%8,%9}, {%0,%1,%2,%3};"
                 : "+f"(c0), "+f"(c1), "+f"(c2), "+f"(c3)
                 : "r"(a0), "r"(a1), "r"(a2), "r"(a3), "r"(b0), "r"(b1));
}

__device__ __forceinline__ void split3(float x, __half& h1, __half& h2, __half& h3) {
    h1 = __float2half_rn(x);
    float r1 = x - __half2float(h1);
    h2 = __float2half_rn(r1);
    float r2 = r1 - __half2float(h2);
    h3 = __float2half_rn(r2);
}

// =====================================================================
// Prep: normalize codebook -> g_en, g_bias, split rows g_Bp
// =====================================================================
__global__ void prep_kernel(const float* __restrict__ emb) {
    int row  = blockIdx.x * 8 + (threadIdx.x >> 5);
    int lane = threadIdx.x & 31;
    float v  = emb[row * E_DIM + lane];
    float ss = v * v;
    #pragma unroll
    for (int o = 16; o; o >>= 1) ss += __shfl_xor_sync(0xFFFFFFFFu, ss, o);
    float inv = 1.0f / fmaxf(sqrtf(ss), 1e-12f);
    float e = v * inv;
    g_en[row * E_DIM + lane] = e;
    float s2 = e * e;
    #pragma unroll
    for (int o = 16; o; o >>= 1) s2 += __shfl_xor_sync(0xFFFFFFFFu, s2, o);
    if (lane == 0) g_bias[row] = -0.5f * s2;

    __half h1, h2, h3;
    split3(e, h1, h2, h3);
    __half* bp = g_Bp + (size_t)row * KH;
    bp[lane]        = h1;
    bp[32 + lane]   = h1;
    bp[64 + lane]   = h1;
    bp[96 + lane]   = h2;
    bp[128 + lane]  = h2;
    bp[160 + lane]  = h3;
}

// =====================================================================
// Main kernel: 128 tokens/CTA, 8 warps (warp = m16 tile),
// chunks of 128 codes via cp.async double-buffer, HMMA 16x8x16,
// fused argmax + gather + straight-through + loss partial
// =====================================================================
__device__ __forceinline__ void prefetch_chunk(int ch, uint32_t bbase, int tid) {
    int row  = tid >> 1;          // 0..127
    int part = tid & 1;           // halves of a 384B row
    const char* src = (const char*)(g_Bp + (size_t)(ch * NCHUNK + row) * KH) + part * 192;
    uint32_t dst = bbase + row * ROW_B + part * 192;
    #pragma unroll
    for (int i = 0; i < 12; i++)
        CP_ASYNC16(dst + i * 16, src + i * 16);
}

__global__ void __launch_bounds__(256, 1) vq_main_kernel(const float* __restrict__ z,
                                                         float* __restrict__ out) {
    extern __shared__ char smem[];
    const uint32_t sb = smem_u32(smem);
    const int tid  = threadIdx.x;
    const int lane = tid & 31;
    const int w    = tid >> 5;
    const int tok0 = blockIdx.x * MCTA;
    const int g    = lane >> 2;      // fragment row group
    const int tig  = lane & 3;       // thread-in-group (column pair)

    // prefetch first two chunks immediately
    prefetch_chunk(0, sb + B0_OFF, tid); CP_COMMIT();
    prefetch_chunk(1, sb + B1_OFF, tid); CP_COMMIT();

    // build A tile (threads 0-127) | load bias table (threads 128-255)
    if (tid < 128) {
        const int t = tok0 + tid;
        float x[E_DIM];
        const float4* zr = (const float4*)(z + (size_t)t * E_DIM);
        float ss = 0.0f;
        #pragma unroll
        for (int j = 0; j < 8; j++) {
            float4 v = zr[j];
            x[4*j+0] = v.x; x[4*j+1] = v.y; x[4*j+2] = v.z; x[4*j+3] = v.w;
            ss += v.x*v.x + v.y*v.y + v.z*v.z + v.w*v.w;
        }
        float inv = 1.0f / fmaxf(sqrtf(ss), 1e-12f);
        __half* arow = (__half*)(smem + A_OFF + tid * ROW_B);
        #pragma unroll
        for (int d = 0; d < E_DIM; d++) {
            __half h1, h2, h3;
            split3(x[d] * inv, h1, h2, h3);
            arow[d]        = h1;   // pairs with B h1
            arow[32 + d]   = h2;   // pairs with B h1
            arow[64 + d]   = h3;   // pairs with B h1
            arow[96 + d]   = h1;   // pairs with B h2
            arow[128 + d]  = h2;   // pairs with B h2
            arow[160 + d]  = h1;   // pairs with B h3
        }
    } else {
        float4* sbias4 = (float4*)(smem + BIAS_OFF);
        const float4* gb4 = (const float4*)g_bias;
        int t2 = tid - 128;
        #pragma unroll
        for (int i = 0; i < 16; i++)
            sbias4[i * 128 + t2] = gb4[i * 128 + t2];
    }
    __syncthreads();

    // load A fragments once (48 regs)
    uint32_t af[KSTEPS][4];
    {
        const uint32_t* aw = (const uint32_t*)(smem + A_OFF);
        const int r0 = w * 16 + g;
        #pragma unroll
        for (int ks = 0; ks < KSTEPS; ks++) {
            int base = ks * 8 + tig;
            af[ks][0] = aw[r0 * ROW_W + base];
            af[ks][1] = aw[(r0 + 8) * ROW_W + base];
            af[ks][2] = aw[r0 * ROW_W + base + 4];
            af[ks][3] = aw[(r0 + 8) * ROW_W + base + 4];
        }
    }

    const float* sbias = (const float*)(smem + BIAS_OFF);
    float bestA = -3.4e38f, bestB = -3.4e38f;
    int   idxA = 0, idxB = 0;

    for (int ch = 0; ch < CHUNKS; ch++) {
        CP_WAIT1();
        __syncthreads();
        const uint32_t bbase = sb + ((ch & 1) ? B1_OFF : B0_OFF);
        const uint32_t* bw = (const uint32_t*)(smem + ((ch & 1) ? B1_OFF : B0_OFF));
        const int nbase = ch * NCHUNK;

        #pragma unroll 4
        for (int nt = 0; nt < 16; nt++) {
            const uint32_t* brow = bw + (nt * 8 + g) * ROW_W;
            float c0 = 0.0f, c1 = 0.0f, c2 = 0.0f, c3 = 0.0f;
            #pragma unroll
            for (int ks = 0; ks < KSTEPS; ks++) {
                uint32_t b0 = brow[ks * 8 + tig];
                uint32_t b1 = brow[ks * 8 + tig + 4];
                mma16816(c0, c1, c2, c3, af[ks][0], af[ks][1], af[ks][2], af[ks][3], b0, b1);
            }
            int n0 = nbase + nt * 8 + 2 * tig;
            float bias0 = sbias[n0], bias1 = sbias[n0 + 1];
            float s0 = c0 + bias0, s1 = c1 + bias1;
            float s2 = c2 + bias0, s3 = c3 + bias1;
            if (s0 > bestA) { bestA = s0; idxA = n0; }
            if (s1 > bestA) { bestA = s1; idxA = n0 + 1; }
            if (s2 > bestB) { bestB = s2; idxB = n0; }
            if (s3 > bestB) { bestB = s3; idxB = n0 + 1; }
        }
        __syncthreads();
        if (ch + 2 < CHUNKS) prefetch_chunk(ch + 2, bbase, tid);
        CP_COMMIT();
    }

    // cross-lane argmax reduce within each row group (tie -> smaller index)
    #pragma unroll
    for (int o = 1; o <= 2; o <<= 1) {
        float sA = __shfl_xor_sync(0xFFFFFFFFu, bestA, o);
        int   jA = __shfl_xor_sync(0xFFFFFFFFu, idxA,  o);
        if (sA > bestA || (sA == bestA && jA < idxA)) { bestA = sA; idxA = jA; }
        float sB = __shfl_xor_sync(0xFFFFFFFFu, bestB, o);
        int   jB = __shfl_xor_sync(0xFFFFFFFFu, idxB,  o);
        if (sB > bestB || (sB == bestB && jB < idxB)) { bestB = sB; idxB = jB; }
    }
    int* s_bidx = (int*)smem;   // reuse A region (frags live in regs)
    if (tig == 0) {
        s_bidx[w * 16 + g]     = idxA;
        s_bidx[w * 16 + 8 + g] = idxB;
    }
    __syncthreads();

    // ---- epilogue: gather, straight-through output, loss partial ----
    float lsum = 0.0f;
    if (tid < 128) {
        const int t  = tok0 + tid;
        const int bi = s_bidx[tid];
        float zn[E_DIM];
        const float4* zr = (const float4*)(z + (size_t)t * E_DIM);
        float ss = 0.0f;
        #pragma unroll
        for (int j = 0; j < 8; j++) {
            float4 v = zr[j];
            zn[4*j+0] = v.x; zn[4*j+1] = v.y; zn[4*j+2] = v.z; zn[4*j+3] = v.w;
            ss += v.x*v.x + v.y*v.y + v.z*v.z + v.w*v.w;
        }
        float inv = 1.0f / fmaxf(sqrtf(ss), 1e-12f);
        #pragma unroll
        for (int d = 0; d < E_DIM; d++) zn[d] *= inv;

        float o[E_DIM];
        const float* eq = g_en + (size_t)bi * E_DIM;
        #pragma unroll
        for (int d = 0; d < E_DIM; d++) {
            float df = eq[d] - zn[d];
            lsum += df * df;
            o[d] = zn[d] + df;
        }
        float4* orow = (float4*)(out + (size_t)t * E_DIM);
        #pragma unroll
        for (int j = 0; j < 8; j++)
            orow[j] = make_float4(o[4*j], o[4*j+1], o[4*j+2], o[4*j+3]);
        out[(size_t)T_TOK * E_DIM + 1 + t] = (float)bi;
    }

    __syncthreads();   // s_bidx reads done before reuse as reduction buffer
    float* s_red = (float*)smem;
    s_red[tid] = lsum;
    __syncthreads();
    #pragma unroll
    for (int k = 128; k; k >>= 1) {
        if (tid < k) s_red[tid] += s_red[tid + k];
        __syncthreads();
    }
    if (tid == 0) g_part[blockIdx.x] = s_red[0];
}

// =====================================================================
// Final loss: 1.25 * sum / (T*D)
// =====================================================================
__global__ void finish_kernel(float* __restrict__ out) {
    __shared__ float s[256];
    int tid = threadIdx.x;
    s[tid] = g_part[tid];
    __syncthreads();
    #pragma unroll
    for (int k = 128; k; k >>= 1) {
        if (tid < k) s[tid] += s[tid + k];
        __syncthreads();
    }
    if (tid == 0) out[(size_t)T_TOK * E_DIM] = 1.25f * s[0] / (float)(T_TOK * E_DIM);
}

extern "C" void kernel_launch(void* const* d_in, const int* in_sizes, int n_in,
                              void* d_out, int out_size) {
    const float* z   = (const float*)d_in[0];
    const float* emb = (const float*)d_in[1];
    float* out = (float*)d_out;

    cudaFuncSetAttribute(vq_main_kernel, cudaFuncAttributeMaxDynamicSharedMemorySize, SMEM_TOTAL);

    prep_kernel<<<N_E / 8, 256>>>(emb);
    vq_main_kernel<<<GRID_MAIN, 256, SMEM_TOTAL>>>(z, out);
    finish_kernel<<<1, 256>>>(out);
}

// round 5
// speedup vs baseline: 5.0558x; 1.5255x over previous
#include <cuda_runtime.h>
#include <cuda_fp16.h>
#include <math.h>
#include <stdint.h>

#define N_E    8192
#define E_DIM  32
#define T_TOK  32768
#define KH     96             // halfs per row: 3 blocks of 32
#define KSTEPS 6
#define ROW_B  208            // smem row stride bytes (104 halfs) -> conflict-free
#define ROW_W  52
#define NCHUNK 128
#define CHUNKS 64
#define MCTA   128
#define GRID_MAIN 256
#define WINDOW 1e-5f
#define CAND_CAP 16

// ---- device scratch ----
__device__ float  g_en  [N_E * E_DIM];   // normalized codebook fp32 (rescore/gather)
__device__ float  g_bias[N_E];           // -0.5 * ||en||^2
__device__ __half g_Bp  [N_E * KH];      // split codebook rows [h1|h1|h2]
__device__ float  g_part[GRID_MAIN];

// ---- smem layout (bytes) ----
#define A_OFF    0
#define B0_OFF   26624
#define B1_OFF   53248
#define BIAS_OFF 79872
#define SMEM_TOTAL 112640
// candidate lists reuse B0 after the mainloop:
//   cnt[128] ints at B0, list[128][16] ints at B0+512

#define CP_ASYNC16(s, g) asm volatile("cp.async.cg.shared.global [%0], [%1], 16;" :: "r"(s), "l"(g) : "memory")
#define CP_COMMIT()      asm volatile("cp.async.commit_group;" ::: "memory")
#define CP_WAIT1()       asm volatile("cp.async.wait_group 1;" ::: "memory")
#define CP_WAIT0()       asm volatile("cp.async.wait_group 0;" ::: "memory")

__device__ __forceinline__ uint32_t smem_u32(const void* p) {
    uint32_t a;
    asm("{ .reg .u64 t; cvta.to.shared.u64 t, %1; cvt.u32.u64 %0, t; }" : "=r"(a) : "l"(p));
    return a;
}

__device__ __forceinline__ void mma16816(float& c0, float& c1, float& c2, float& c3,
                                         uint32_t a0, uint32_t a1, uint32_t a2, uint32_t a3,
                                         uint32_t b0, uint32_t b1) {
    asm volatile("mma.sync.aligned.m16n8k16.row.col.f32.f16.f16.f32 "
                 "{%0,%1,%2,%3}, {%4,%5,%6,%7}, {%8,%9}, {%0,%1,%2,%3};"
                 : "+f"(c0), "+f"(c1), "+f"(c2), "+f"(c3)
                 : "r"(a0), "r"(a1), "r"(a2), "r"(a3), "r"(b0), "r"(b1));
}

__device__ __forceinline__ void split2(float x, __half& h1, __half& h2) {
    h1 = __float2half_rn(x);
    h2 = __float2half_rn(x - __half2float(h1));
}

// =====================================================================
// Prep: normalize codebook -> g_en, g_bias, split rows g_Bp = [h1|h1|h2]
// =====================================================================
__global__ void prep_kernel(const float* __restrict__ emb) {
    int row  = blockIdx.x * 8 + (threadIdx.x >> 5);
    int lane = threadIdx.x & 31;
    float v  = emb[row * E_DIM + lane];
    float ss = v * v;
    #pragma unroll
    for (int o = 16; o; o >>= 1) ss += __shfl_xor_sync(0xFFFFFFFFu, ss, o);
    float inv = 1.0f / fmaxf(sqrtf(ss), 1e-12f);
    float e = v * inv;
    g_en[row * E_DIM + lane] = e;
    float s2 = e * e;
    #pragma unroll
    for (int o = 16; o; o >>= 1) s2 += __shfl_xor_sync(0xFFFFFFFFu, s2, o);
    if (lane == 0) g_bias[row] = -0.5f * s2;

    __half h1, h2;
    split2(e, h1, h2);
    __half* bp = g_Bp + (size_t)row * KH;
    bp[lane]      = h1;
    bp[32 + lane] = h1;
    bp[64 + lane] = h2;
}

// =====================================================================
// Main: stage-A coarse GEMM (K=96) + top-2 tracking + candidate window,
// stage-B fp32 rescore + gather + straight-through + loss partial
// =====================================================================
__device__ __forceinline__ void prefetch_chunk(int ch, uint32_t bbase, int tid) {
    int row  = tid >> 1;
    int part = tid & 1;
    const char* src = (const char*)(g_Bp + (size_t)(ch * NCHUNK + row) * KH) + part * 96;
    uint32_t dst = bbase + row * ROW_B + part * 96;
    #pragma unroll
    for (int i = 0; i < 6; i++)
        CP_ASYNC16(dst + i * 16, src + i * 16);
}

#define UPD(s, n, b1, i1, b2, i2)                                  \
    do { float _s = (s); int _n = (n);                             \
         if (_s > (b1)) { (b2) = (b1); (i2) = (i1); (b1) = _s; (i1) = _n; } \
         else if (_s > (b2)) { (b2) = _s; (i2) = _n; } } while (0)

__global__ void __launch_bounds__(256, 1) vq_main_kernel(const float* __restrict__ z,
                                                         float* __restrict__ out) {
    extern __shared__ char smem[];
    const uint32_t sb = smem_u32(smem);
    const int tid  = threadIdx.x;
    const int lane = tid & 31;
    const int w    = tid >> 5;
    const int tok0 = blockIdx.x * MCTA;
    const int g    = lane >> 2;
    const int tig  = lane & 3;

    prefetch_chunk(0, sb + B0_OFF, tid); CP_COMMIT();
    prefetch_chunk(1, sb + B1_OFF, tid); CP_COMMIT();

    // build A tile [h1|h2|h1] (threads 0-127) | load bias table (threads 128-255)
    if (tid < 128) {
        const int t = tok0 + tid;
        float x[E_DIM];
        const float4* zr = (const float4*)(z + (size_t)t * E_DIM);
        float ss = 0.0f;
        #pragma unroll
        for (int j = 0; j < 8; j++) {
            float4 v = zr[j];
            x[4*j+0] = v.x; x[4*j+1] = v.y; x[4*j+2] = v.z; x[4*j+3] = v.w;
            ss += v.x*v.x + v.y*v.y + v.z*v.z + v.w*v.w;
        }
        float inv = 1.0f / fmaxf(sqrtf(ss), 1e-12f);
        __half* arow = (__half*)(smem + A_OFF + tid * ROW_B);
        #pragma unroll
        for (int d = 0; d < E_DIM; d++) {
            __half h1, h2;
            split2(x[d] * inv, h1, h2);
            arow[d]      = h1;   // x B h1
            arow[32 + d] = h2;   // x B h1
            arow[64 + d] = h1;   // x B h2
        }
    } else {
        float4* sbias4 = (float4*)(smem + BIAS_OFF);
        const float4* gb4 = (const float4*)g_bias;
        int t2 = tid - 128;
        #pragma unroll
        for (int i = 0; i < 16; i++)
            sbias4[i * 128 + t2] = gb4[i * 128 + t2];
    }
    __syncthreads();

    // A fragments (24 regs)
    uint32_t af[KSTEPS][4];
    {
        const uint32_t* aw = (const uint32_t*)(smem + A_OFF);
        const int r0 = w * 16 + g;
        #pragma unroll
        for (int ks = 0; ks < KSTEPS; ks++) {
            int base = ks * 8 + tig;
            af[ks][0] = aw[r0 * ROW_W + base];
            af[ks][1] = aw[(r0 + 8) * ROW_W + base];
            af[ks][2] = aw[r0 * ROW_W + base + 4];
            af[ks][3] = aw[(r0 + 8) * ROW_W + base + 4];
        }
    }

    const float* sbias = (const float*)(smem + BIAS_OFF);
    float b1A = -3.4e38f, b2A = -3.4e38f, b1B = -3.4e38f, b2B = -3.4e38f;
    int   i1A = 0, i2A = 0, i1B = 0, i2B = 0;

    for (int ch = 0; ch < CHUNKS; ch++) {
        CP_WAIT1();
        __syncthreads();
        const uint32_t bbase = sb + ((ch & 1) ? B1_OFF : B0_OFF);
        const uint32_t* bw = (const uint32_t*)(smem + ((ch & 1) ? B1_OFF : B0_OFF));
        const int nbase = ch * NCHUNK;

        #pragma unroll 4
        for (int nt = 0; nt < 16; nt++) {
            const uint32_t* brow = bw + (nt * 8 + g) * ROW_W;
            float c0 = 0.0f, c1 = 0.0f, c2 = 0.0f, c3 = 0.0f;
            #pragma unroll
            for (int ks = 0; ks < KSTEPS; ks++) {
                uint32_t b0 = brow[ks * 8 + tig];
                uint32_t b1 = brow[ks * 8 + tig + 4];
                mma16816(c0, c1, c2, c3, af[ks][0], af[ks][1], af[ks][2], af[ks][3], b0, b1);
            }
            int n0 = nbase + nt * 8 + 2 * tig;
            float bias0 = sbias[n0], bias1 = sbias[n0 + 1];
            float s0 = c0 + bias0, s1 = c1 + bias1;
            float s2 = c2 + bias0, s3 = c3 + bias1;
            UPD(s0, n0,     b1A, i1A, b2A, i2A);
            UPD(s1, n0 + 1, b1A, i1A, b2A, i2A);
            UPD(s2, n0,     b1B, i1B, b2B, i2B);
            UPD(s3, n0 + 1, b1B, i1B, b2B, i2B);
        }
        __syncthreads();
        if (ch + 2 < CHUNKS) prefetch_chunk(ch + 2, bbase, tid);
        CP_COMMIT();
    }
    CP_WAIT0();
    __syncthreads();

    // ---- candidate collection into smem lists (reuse B0 region) ----
    int*  s_cnt  = (int*)(smem + B0_OFF);
    int*  s_list = (int*)(smem + B0_OFF + 512);
    if (tid < 128) s_cnt[tid] = 0;
    __syncthreads();

    // token max across the 4 tig lanes
    float mA = b1A, mB = b1B;
    #pragma unroll
    for (int o = 1; o <= 2; o <<= 1) {
        float vA = __shfl_xor_sync(0xFFFFFFFFu, mA, o);
        float vB = __shfl_xor_sync(0xFFFFFFFFu, mB, o);
        mA = fmaxf(mA, vA);
        mB = fmaxf(mB, vB);
    }
    const int tokA = w * 16 + g;
    const int tokB = tokA + 8;
    float thrA = mA - WINDOW, thrB = mB - WINDOW;
    if (b1A >= thrA) { int p = atomicAdd(&s_cnt[tokA], 1); if (p < CAND_CAP) s_list[tokA * CAND_CAP + p] = i1A; }
    if (b2A >= thrA) { int p = atomicAdd(&s_cnt[tokA], 1); if (p < CAND_CAP) s_list[tokA * CAND_CAP + p] = i2A; }
    if (b1B >= thrB) { int p = atomicAdd(&s_cnt[tokB], 1); if (p < CAND_CAP) s_list[tokB * CAND_CAP + p] = i1B; }
    if (b2B >= thrB) { int p = atomicAdd(&s_cnt[tokB], 1); if (p < CAND_CAP) s_list[tokB * CAND_CAP + p] = i2B; }
    __syncthreads();

    // ---- stage B: fp32 rescore + outputs + loss ----
    float lsum = 0.0f;
    if (tid < 128) {
        const int t = tok0 + tid;
        float zn[E_DIM];
        const float4* zr = (const float4*)(z + (size_t)t * E_DIM);
        float ss = 0.0f;
        #pragma unroll
        for (int j = 0; j < 8; j++) {
            float4 v = zr[j];
            zn[4*j+0] = v.x; zn[4*j+1] = v.y; zn[4*j+2] = v.z; zn[4*j+3] = v.w;
            ss += v.x*v.x + v.y*v.y + v.z*v.z + v.w*v.w;
        }
        float inv = 1.0f / fmaxf(sqrtf(ss), 1e-12f);
        #pragma unroll
        for (int d = 0; d < E_DIM; d++) zn[d] *= inv;

        int nc = s_cnt[tid]; if (nc > CAND_CAP) nc = CAND_CAP;
        float best = -3.4e38f;
        int   bi   = 0x7FFFFFFF;
        for (int j = 0; j < nc; j++) {
            int ci = s_list[tid * CAND_CAP + j];
            const float* er = g_en + (size_t)ci * E_DIM;
            float dot = 0.0f;
            #pragma unroll
            for (int d = 0; d < E_DIM; d++) dot = fmaf(zn[d], er[d], dot);
            float s = dot + g_bias[ci];
            if (s > best || (s == best && ci < bi)) { best = s; bi = ci; }
        }

        float o[E_DIM];
        const float* eq = g_en + (size_t)bi * E_DIM;
        #pragma unroll
        for (int d = 0; d < E_DIM; d++) {
            float df = eq[d] - zn[d];
            lsum += df * df;
            o[d] = zn[d] + df;
        }
        float4* orow = (float4*)(out + (size_t)t * E_DIM);
        #pragma unroll
        for (int j = 0; j < 8; j++)
            orow[j] = make_float4(o[4*j], o[4*j+1], o[4*j+2], o[4*j+3]);
        out[(size_t)T_TOK * E_DIM + 1 + t] = (float)bi;
    }

    __syncthreads();
    float* s_red = (float*)smem;
    s_red[tid] = lsum;
    __syncthreads();
    #pragma unroll
    for (int k = 128; k; k >>= 1) {
        if (tid < k) s_red[tid] += s_red[tid + k];
        __syncthreads();
    }
    if (tid == 0) g_part[blockIdx.x] = s_red[0];
}

// =====================================================================
// Final loss: 1.25 * sum / (T*D)
// =====================================================================
__global__ void finish_kernel(float* __restrict__ out) {
    __shared__ float s[256];
    int tid = threadIdx.x;
    s[tid] = g_part[tid];
    __syncthreads();
    #pragma unroll
    for (int k = 128; k; k >>= 1) {
        if (tid < k) s[tid] += s[tid + k];
        __syncthreads();
    }
    if (tid == 0) out[(size_t)T_TOK * E_DIM] = 1.25f * s[0] / (float)(T_TOK * E_DIM);
}

extern "C" void kernel_launch(void* const* d_in, const int* in_sizes, int n_in,
                              void* d_out, int out_size) {
    const float* z   = (const float*)d_in[0];
    const float* emb = (const float*)d_in[1];
    float* out = (float*)d_out;

    cudaFuncSetAttribute(vq_main_kernel, cudaFuncAttributeMaxDynamicSharedMemorySize, SMEM_TOTAL);

    prep_kernel<<<N_E / 8, 256>>>(emb);
    vq_main_kernel<<<GRID_MAIN, 256, SMEM_TOTAL>>>(z, out);
    finish_kernel<<<1, 256>>>(out);
}

// round 6
// speedup vs baseline: 8.5014x; 1.6815x over previous
#include <cuda_runtime.h>
#include <cuda_fp16.h>
#include <math.h>
#include <stdint.h>

#define N_E    8192
#define E_DIM  32
#define T_TOK  32768
#define KH     32             // coarse K: single fp16 block (pure h1)
#define ROW_B  80             // smem row stride bytes (conflict-free, 16B aligned)
#define ROW_W  20
#define NCHUNK 256
#define CHUNKS 32
#define MCTA   128
#define GRID_MAIN 256
#define WINDOW 4e-3f
#define CAND_CAP 16

// ---- device scratch ----
__device__ float  g_en  [N_E * E_DIM];   // normalized codebook fp32 (rescore/gather)
__device__ float  g_bias[N_E];           // -0.5 * ||en||^2 (stage-B rescore only)
__device__ __half g_Bp  [N_E * KH];      // fp16 codebook rows
__device__ float  g_part[GRID_MAIN];

// ---- smem layout (bytes) ----
#define A_OFF    0
#define B0_OFF   10240
#define B1_OFF   30720
#define SMEM_TOTAL 51456
// candidate lists reuse B0 after mainloop: cnt[128] @B0, list[128][16] @B0+512

#define CP_ASYNC16(s, g) asm volatile("cp.async.cg.shared.global [%0], [%1], 16;" :: "r"(s), "l"(g) : "memory")
#define CP_COMMIT()      asm volatile("cp.async.commit_group;" ::: "memory")
#define CP_WAIT1()       asm volatile("cp.async.wait_group 1;" ::: "memory")
#define CP_WAIT0()       asm volatile("cp.async.wait_group 0;" ::: "memory")

__device__ __forceinline__ uint32_t smem_u32(const void* p) {
    uint32_t a;
    asm("{ .reg .u64 t; cvta.to.shared.u64 t, %1; cvt.u32.u64 %0, t; }" : "=r"(a) : "l"(p));
    return a;
}

__device__ __forceinline__ void mma16816(float& c0, float& c1, float& c2, float& c3,
                                         uint32_t a0, uint32_t a1, uint32_t a2, uint32_t a3,
                                         uint32_t b0, uint32_t b1) {
    asm volatile("mma.sync.aligned.m16n8k16.row.col.f32.f16.f16.f32 "
                 "{%0,%1,%2,%3}, {%4,%5,%6,%7}, {%8,%9}, {%0,%1,%2,%3};"
                 : "+f"(c0), "+f"(c1), "+f"(c2), "+f"(c3)
                 : "r"(a0), "r"(a1), "r"(a2), "r"(a3), "r"(b0), "r"(b1));
}

// rare-path top-3 insertion
#define INS3(s, n, b1, i1, b2, i2, b3, i3)                                     \
    do { float _s = (s); int _n = (n);                                         \
         if (_s > (b3)) {                                                      \
             if (_s > (b1)) { (b3)=(b2); (i3)=(i2); (b2)=(b1); (i2)=(i1); (b1)=_s; (i1)=_n; } \
             else if (_s > (b2)) { (b3)=(b2); (i3)=(i2); (b2)=_s; (i2)=_n; }   \
             else { (b3)=_s; (i3)=_n; }                                        \
         } } while (0)

// =====================================================================
// Prep: normalize codebook -> g_en (fp32), g_bias, fp16 rows g_Bp
// =====================================================================
__global__ void prep_kernel(const float* __restrict__ emb) {
    int row  = blockIdx.x * 8 + (threadIdx.x >> 5);
    int lane = threadIdx.x & 31;
    float v  = emb[row * E_DIM + lane];
    float ss = v * v;
    #pragma unroll
    for (int o = 16; o; o >>= 1) ss += __shfl_xor_sync(0xFFFFFFFFu, ss, o);
    float inv = 1.0f / fmaxf(sqrtf(ss), 1e-12f);
    float e = v * inv;
    g_en[row * E_DIM + lane] = e;
    float s2 = e * e;
    #pragma unroll
    for (int o = 16; o; o >>= 1) s2 += __shfl_xor_sync(0xFFFFFFFFu, s2, o);
    if (lane == 0) g_bias[row] = -0.5f * s2;
    g_Bp[(size_t)row * KH + lane] = __float2half_rn(e);
}

// =====================================================================
// Main: K=32 coarse HMMA + top-3/thread window candidates, fp32 rescore
// =====================================================================
__device__ __forceinline__ void prefetch_chunk(int ch, uint32_t bbase, int tid) {
    const char* src = (const char*)(g_Bp + (size_t)(ch * NCHUNK + tid) * KH);
    uint32_t dst = bbase + tid * ROW_B;
    #pragma unroll
    for (int i = 0; i < 4; i++)
        CP_ASYNC16(dst + i * 16, src + i * 16);
}

__global__ void __launch_bounds__(256, 2) vq_main_kernel(const float* __restrict__ z,
                                                         float* __restrict__ out) {
    extern __shared__ char smem[];
    const uint32_t sb = smem_u32(smem);
    const int tid  = threadIdx.x;
    const int lane = tid & 31;
    const int w    = tid >> 5;
    const int tok0 = blockIdx.x * MCTA;
    const int g    = lane >> 2;
    const int tig  = lane & 3;

    prefetch_chunk(0, sb + B0_OFF, tid); CP_COMMIT();
    prefetch_chunk(1, sb + B1_OFF, tid); CP_COMMIT();

    // build A tile (threads 0-127): one token per thread, plain fp16
    if (tid < 128) {
        const int t = tok0 + tid;
        float x[E_DIM];
        const float4* zr = (const float4*)(z + (size_t)t * E_DIM);
        float ss = 0.0f;
        #pragma unroll
        for (int j = 0; j < 8; j++) {
            float4 v = zr[j];
            x[4*j+0] = v.x; x[4*j+1] = v.y; x[4*j+2] = v.z; x[4*j+3] = v.w;
            ss += v.x*v.x + v.y*v.y + v.z*v.z + v.w*v.w;
        }
        float inv = 1.0f / fmaxf(sqrtf(ss), 1e-12f);
        __half* arow = (__half*)(smem + A_OFF + tid * ROW_B);
        #pragma unroll
        for (int d = 0; d < E_DIM; d++)
            arow[d] = __float2half_rn(x[d] * inv);
    }
    __syncthreads();

    // A fragments: 2 ksteps x 4 regs
    uint32_t af[2][4];
    {
        const uint32_t* aw = (const uint32_t*)(smem + A_OFF);
        const int r0 = w * 16 + g;
        #pragma unroll
        for (int ks = 0; ks < 2; ks++) {
            int base = ks * 8 + tig;
            af[ks][0] = aw[r0 * ROW_W + base];
            af[ks][1] = aw[(r0 + 8) * ROW_W + base];
            af[ks][2] = aw[r0 * ROW_W + base + 4];
            af[ks][3] = aw[(r0 + 8) * ROW_W + base + 4];
        }
    }

    float b1A = -3.4e38f, b2A = -3.4e38f, b3A = -3.4e38f;
    float b1B = -3.4e38f, b2B = -3.4e38f, b3B = -3.4e38f;
    int   i1A = 0, i2A = 0, i3A = 0, i1B = 0, i2B = 0, i3B = 0;

    for (int ch = 0; ch < CHUNKS; ch++) {
        CP_WAIT1();
        __syncthreads();
        const uint32_t bbase = sb + ((ch & 1) ? B1_OFF : B0_OFF);
        const uint32_t* bw = (const uint32_t*)(smem + ((ch & 1) ? B1_OFF : B0_OFF));
        const int nbase = ch * NCHUNK;

        #pragma unroll 4
        for (int nt = 0; nt < 32; nt++) {
            const uint32_t* brow = bw + (nt * 8 + g) * ROW_W;
            float c0 = 0.0f, c1 = 0.0f, c2 = 0.0f, c3 = 0.0f;
            #pragma unroll
            for (int ks = 0; ks < 2; ks++) {
                uint32_t b0 = brow[ks * 8 + tig];
                uint32_t b1 = brow[ks * 8 + tig + 4];
                mma16816(c0, c1, c2, c3, af[ks][0], af[ks][1], af[ks][2], af[ks][3], b0, b1);
            }
            int n0 = nbase + nt * 8 + 2 * tig;
            // fast path: most scores never beat running 3rd-best
            float mA = fmaxf(c0, c1);
            if (mA > b3A) {
                INS3(c0, n0,     b1A, i1A, b2A, i2A, b3A, i3A);
                INS3(c1, n0 + 1, b1A, i1A, b2A, i2A, b3A, i3A);
            }
            float mB = fmaxf(c2, c3);
            if (mB > b3B) {
                INS3(c2, n0,     b1B, i1B, b2B, i2B, b3B, i3B);
                INS3(c3, n0 + 1, b1B, i1B, b2B, i2B, b3B, i3B);
            }
        }
        __syncthreads();
        if (ch + 2 < CHUNKS) prefetch_chunk(ch + 2, bbase, tid);
        CP_COMMIT();
    }
    CP_WAIT0();
    __syncthreads();

    // ---- candidate collection (reuse B0 region) ----
    int* s_cnt  = (int*)(smem + B0_OFF);
    int* s_list = (int*)(smem + B0_OFF + 512);
    if (tid < 128) s_cnt[tid] = 0;
    __syncthreads();

    float mA = b1A, mB = b1B;
    #pragma unroll
    for (int o = 1; o <= 2; o <<= 1) {
        mA = fmaxf(mA, __shfl_xor_sync(0xFFFFFFFFu, mA, o));
        mB = fmaxf(mB, __shfl_xor_sync(0xFFFFFFFFu, mB, o));
    }
    const int tokA = w * 16 + g;
    const int tokB = tokA + 8;
    float thrA = mA - WINDOW, thrB = mB - WINDOW;
    if (b1A >= thrA) { int p = atomicAdd(&s_cnt[tokA], 1); if (p < CAND_CAP) s_list[tokA * CAND_CAP + p] = i1A; }
    if (b2A >= thrA) { int p = atomicAdd(&s_cnt[tokA], 1); if (p < CAND_CAP) s_list[tokA * CAND_CAP + p] = i2A; }
    if (b3A >= thrA) { int p = atomicAdd(&s_cnt[tokA], 1); if (p < CAND_CAP) s_list[tokA * CAND_CAP + p] = i3A; }
    if (b1B >= thrB) { int p = atomicAdd(&s_cnt[tokB], 1); if (p < CAND_CAP) s_list[tokB * CAND_CAP + p] = i1B; }
    if (b2B >= thrB) { int p = atomicAdd(&s_cnt[tokB], 1); if (p < CAND_CAP) s_list[tokB * CAND_CAP + p] = i2B; }
    if (b3B >= thrB) { int p = atomicAdd(&s_cnt[tokB], 1); if (p < CAND_CAP) s_list[tokB * CAND_CAP + p] = i3B; }
    __syncthreads();

    // ---- stage B: fp32 rescore + outputs + loss ----
    float lsum = 0.0f;
    if (tid < 128) {
        const int t = tok0 + tid;
        float zn[E_DIM];
        const float4* zr = (const float4*)(z + (size_t)t * E_DIM);
        float ss = 0.0f;
        #pragma unroll
        for (int j = 0; j < 8; j++) {
            float4 v = zr[j];
            zn[4*j+0] = v.x; zn[4*j+1] = v.y; zn[4*j+2] = v.z; zn[4*j+3] = v.w;
            ss += v.x*v.x + v.y*v.y + v.z*v.z + v.w*v.w;
        }
        float inv = 1.0f / fmaxf(sqrtf(ss), 1e-12f);
        #pragma unroll
        for (int d = 0; d < E_DIM; d++) zn[d] *= inv;

        int nc = s_cnt[tid]; if (nc > CAND_CAP) nc = CAND_CAP;
        float best = -3.4e38f;
        int   bi   = 0x7FFFFFFF;
        for (int j = 0; j < nc; j++) {
            int ci = s_list[tid * CAND_CAP + j];
            const float* er = g_en + (size_t)ci * E_DIM;
            float dot = 0.0f;
            #pragma unroll
            for (int d = 0; d < E_DIM; d++) dot = fmaf(zn[d], er[d], dot);
            float s = dot + g_bias[ci];
            if (s > best || (s == best && ci < bi)) { best = s; bi = ci; }
        }

        float o[E_DIM];
        const float* eq = g_en + (size_t)bi * E_DIM;
        #pragma unroll
        for (int d = 0; d < E_DIM; d++) {
            float df = eq[d] - zn[d];
            lsum += df * df;
            o[d] = zn[d] + df;
        }
        float4* orow = (float4*)(out + (size_t)t * E_DIM);
        #pragma unroll
        for (int j = 0; j < 8; j++)
            orow[j] = make_float4(o[4*j], o[4*j+1], o[4*j+2], o[4*j+3]);
        out[(size_t)T_TOK * E_DIM + 1 + t] = (float)bi;
    }

    __syncthreads();
    float* s_red = (float*)smem;
    s_red[tid] = lsum;
    __syncthreads();
    #pragma unroll
    for (int k = 128; k; k >>= 1) {
        if (tid < k) s_red[tid] += s_red[tid + k];
        __syncthreads();
    }
    if (tid == 0) g_part[blockIdx.x] = s_red[0];
}

// =====================================================================
// Final loss: 1.25 * sum / (T*D)
// =====================================================================
__global__ void finish_kernel(float* __restrict__ out) {
    __shared__ float s[256];
    int tid = threadIdx.x;
    s[tid] = g_part[tid];
    __syncthreads();
    #pragma unroll
    for (int k = 128; k; k >>= 1) {
        if (tid < k) s[tid] += s[tid + k];
        __syncthreads();
    }
    if (tid == 0) out[(size_t)T_TOK * E_DIM] = 1.25f * s[0] / (float)(T_TOK * E_DIM);
}

extern "C" void kernel_launch(void* const* d_in, const int* in_sizes, int n_in,
                              void* d_out, int out_size) {
    const float* z   = (const float*)d_in[0];
    const float* emb = (const float*)d_in[1];
    float* out = (float*)d_out;

    cudaFuncSetAttribute(vq_main_kernel, cudaFuncAttributeMaxDynamicSharedMemorySize, SMEM_TOTAL);

    prep_kernel<<<N_E / 8, 256>>>(emb);
    vq_main_kernel<<<GRID_MAIN, 256, SMEM_TOTAL>>>(z, out);
    finish_kernel<<<1, 256>>>(out);
}